// round 1
// baseline (speedup 1.0000x reference)
#include <cuda_runtime.h>
#include <math.h>

// Problem constants
#define Bc   2
#define Sc   2048
#define Dc   1024
#define Hc   16
#define HDc  64
#define Mtot (Bc * Sc)          // 4096
#define SCALE 0.03125f          // 1/sqrt(1024)

// Scratch (device globals: alloc-free rule)
__device__ float g_q[(size_t)Bc * Hc * Sc * HDc];     // [b,h,s,d] 16 MB
__device__ float g_k[(size_t)Bc * Hc * Sc * HDc];
__device__ float g_v[(size_t)Bc * Hc * Sc * HDc];
__device__ float g_attn[(size_t)Bc * Sc * Dc];        // [b,s,D]  16 MB

// ---------------------------------------------------------------------------
// Tiled SGEMM: C[M,N] = A[M,K] @ B[K,N] + bias[N]
// 128x128 block tile, BK=8, 256 threads, 8x8 micro-tile per thread.
// MODE 0: A = param (X), epilogue scatters into g_q/g_k/g_v ([b,h,s,hd] layout)
// MODE 1: A = g_attn, plain epilogue + bias into C (d_out)
// Requires M%128==0, N%128==0, K%8==0 (true for all calls here).
// ---------------------------------------------------------------------------
template <int MODE>
__global__ __launch_bounds__(256)
void sgemm128(const float* __restrict__ A, const float* __restrict__ Bm,
              const float* __restrict__ bias, float* __restrict__ C,
              int M, int N, int K)
{
    __shared__ float As[8][128];   // transposed A tile
    __shared__ float Bs[8][128];

    const int tid = threadIdx.x;
    const int bm = blockIdx.y * 128;
    const int bn = blockIdx.x * 128;

    const int aRow = tid >> 1;            // 0..127
    const int aCol = (tid & 1) << 2;      // 0 or 4
    const int bRow = tid >> 5;            // 0..7
    const int bCol = (tid & 31) << 2;     // 0..124

    const int tx = tid & 15;              // col micro-tile
    const int ty = tid >> 4;              // row micro-tile

    const float* Ap = (MODE == 1) ? g_attn : A;

    float acc[8][8];
#pragma unroll
    for (int i = 0; i < 8; i++)
#pragma unroll
        for (int j = 0; j < 8; j++) acc[i][j] = 0.f;

    const float* Aload = Ap + (size_t)(bm + aRow) * K + aCol;
    const float* Bload = Bm + (size_t)bRow * N + bn + bCol;

    for (int k0 = 0; k0 < K; k0 += 8) {
        float4 a4 = *reinterpret_cast<const float4*>(Aload + k0);
        float4 b4 = *reinterpret_cast<const float4*>(Bload + (size_t)k0 * N);
        As[aCol + 0][aRow] = a4.x;
        As[aCol + 1][aRow] = a4.y;
        As[aCol + 2][aRow] = a4.z;
        As[aCol + 3][aRow] = a4.w;
        *reinterpret_cast<float4*>(&Bs[bRow][bCol]) = b4;
        __syncthreads();

#pragma unroll
        for (int kk = 0; kk < 8; kk++) {
            float4 ra0 = *reinterpret_cast<const float4*>(&As[kk][ty * 8]);
            float4 ra1 = *reinterpret_cast<const float4*>(&As[kk][ty * 8 + 4]);
            float4 rb0 = *reinterpret_cast<const float4*>(&Bs[kk][tx * 8]);
            float4 rb1 = *reinterpret_cast<const float4*>(&Bs[kk][tx * 8 + 4]);
            float ra[8] = {ra0.x, ra0.y, ra0.z, ra0.w, ra1.x, ra1.y, ra1.z, ra1.w};
            float rb[8] = {rb0.x, rb0.y, rb0.z, rb0.w, rb1.x, rb1.y, rb1.z, rb1.w};
#pragma unroll
            for (int i = 0; i < 8; i++)
#pragma unroll
                for (int j = 0; j < 8; j++)
                    acc[i][j] += ra[i] * rb[j];
        }
        __syncthreads();
    }

    const int col0 = bn + tx * 8;
    float bv[8];
    {
        float4 bb0 = *reinterpret_cast<const float4*>(bias + col0);
        float4 bb1 = *reinterpret_cast<const float4*>(bias + col0 + 4);
        bv[0] = bb0.x; bv[1] = bb0.y; bv[2] = bb0.z; bv[3] = bb0.w;
        bv[4] = bb1.x; bv[5] = bb1.y; bv[6] = bb1.z; bv[7] = bb1.w;
    }

    if (MODE == 1) {
#pragma unroll
        for (int i = 0; i < 8; i++) {
            const int row = bm + ty * 8 + i;
            float4 o0, o1;
            o0.x = acc[i][0] + bv[0]; o0.y = acc[i][1] + bv[1];
            o0.z = acc[i][2] + bv[2]; o0.w = acc[i][3] + bv[3];
            o1.x = acc[i][4] + bv[4]; o1.y = acc[i][5] + bv[5];
            o1.z = acc[i][6] + bv[6]; o1.w = acc[i][7] + bv[7];
            *reinterpret_cast<float4*>(C + (size_t)row * N + col0) = o0;
            *reinterpret_cast<float4*>(C + (size_t)row * N + col0 + 4) = o1;
        }
    } else {
        // QKV scatter: column col0 (aligned to 8, within one head & one of q/k/v)
        const int qkv = col0 >> 10;           // 0,1,2
        const int rest = col0 & 1023;
        const int h = rest >> 6;
        const int c0 = rest & 63;
        float* dstBase = (qkv == 0) ? g_q : ((qkv == 1) ? g_k : g_v);
#pragma unroll
        for (int i = 0; i < 8; i++) {
            const int m = bm + ty * 8 + i;
            const int b = m >> 11;            // /S (2048)
            const int s = m & (Sc - 1);
            float* dst = dstBase + ((((size_t)b * Hc + h) * Sc + s) * HDc + c0);
            float4 o0, o1;
            o0.x = acc[i][0] + bv[0]; o0.y = acc[i][1] + bv[1];
            o0.z = acc[i][2] + bv[2]; o0.w = acc[i][3] + bv[3];
            o1.x = acc[i][4] + bv[4]; o1.y = acc[i][5] + bv[5];
            o1.z = acc[i][6] + bv[6]; o1.w = acc[i][7] + bv[7];
            *reinterpret_cast<float4*>(dst) = o0;
            *reinterpret_cast<float4*>(dst + 4) = o1;
        }
    }
}

// ---------------------------------------------------------------------------
// Flash attention fp32, one query per thread. Grid: (S/128, B*H), 128 threads.
// Q/K/V in [b,h,s,hd] scratch. Writes g_attn[b,s,h*hd+d]. Causal.
// ---------------------------------------------------------------------------
#define TKEYS 64

__global__ __launch_bounds__(128)
void attn_kernel()
{
    const int bh = blockIdx.y;                      // 0..B*H-1
    const int b = bh / Hc;
    const int h = bh % Hc;
    const int qi = blockIdx.x * 128 + threadIdx.x;  // query index

    __shared__ float Ks[TKEYS][HDc];
    __shared__ float Vs[TKEYS][HDc];

    // Load q (scale folded in)
    float q[HDc];
    {
        const float* Qg = g_q + ((size_t)bh * Sc + qi) * HDc;
#pragma unroll
        for (int d4 = 0; d4 < HDc / 4; d4++) {
            float4 t = *reinterpret_cast<const float4*>(Qg + d4 * 4);
            q[d4 * 4 + 0] = t.x * SCALE;
            q[d4 * 4 + 1] = t.y * SCALE;
            q[d4 * 4 + 2] = t.z * SCALE;
            q[d4 * 4 + 3] = t.w * SCALE;
        }
    }

    float o[HDc];
#pragma unroll
    for (int d = 0; d < HDc; d++) o[d] = 0.f;
    float mrun = -INFINITY;
    float lrun = 0.f;

    const int kmax = blockIdx.x * 128 + 127;        // max key this block needs (inclusive)
    const float* Kg0 = g_k + (size_t)bh * Sc * HDc;
    const float* Vg0 = g_v + (size_t)bh * Sc * HDc;

    for (int kt = 0; kt <= kmax; kt += TKEYS) {
        // cooperative tile load: TKEYS*64 floats = 1024 float4 per array
        {
            const float4* Kg = reinterpret_cast<const float4*>(Kg0 + (size_t)kt * HDc);
            const float4* Vg = reinterpret_cast<const float4*>(Vg0 + (size_t)kt * HDc);
            float4* Kd = reinterpret_cast<float4*>(&Ks[0][0]);
            float4* Vd = reinterpret_cast<float4*>(&Vs[0][0]);
#pragma unroll
            for (int i = 0; i < (TKEYS * HDc / 4) / 128; i++) {
                Kd[threadIdx.x + i * 128] = Kg[threadIdx.x + i * 128];
                Vd[threadIdx.x + i * 128] = Vg[threadIdx.x + i * 128];
            }
        }
        __syncthreads();

        const int klim = min(TKEYS, qi - kt + 1);   // causal bound (can be <=0)
        for (int kk = 0; kk < klim; kk++) {
            float s = 0.f;
#pragma unroll
            for (int d4 = 0; d4 < HDc / 4; d4++) {
                float4 kv = *reinterpret_cast<const float4*>(&Ks[kk][d4 * 4]);
                s += q[d4 * 4 + 0] * kv.x;
                s += q[d4 * 4 + 1] * kv.y;
                s += q[d4 * 4 + 2] * kv.z;
                s += q[d4 * 4 + 3] * kv.w;
            }
            if (s > mrun) {                          // lazy rescale
                const float corr = __expf(mrun - s); // 0 on first hit (mrun=-inf)
                mrun = s;
                lrun *= corr;
#pragma unroll
                for (int d = 0; d < HDc; d++) o[d] *= corr;
            }
            const float p = __expf(s - mrun);
            lrun += p;
#pragma unroll
            for (int d4 = 0; d4 < HDc / 4; d4++) {
                float4 vv = *reinterpret_cast<const float4*>(&Vs[kk][d4 * 4]);
                o[d4 * 4 + 0] += p * vv.x;
                o[d4 * 4 + 1] += p * vv.y;
                o[d4 * 4 + 2] += p * vv.z;
                o[d4 * 4 + 3] += p * vv.w;
            }
        }
        __syncthreads();
    }

    const float inv = 1.f / lrun;
    float* Og = g_attn + ((size_t)b * Sc + qi) * Dc + h * HDc;
#pragma unroll
    for (int d4 = 0; d4 < HDc / 4; d4++) {
        float4 t;
        t.x = o[d4 * 4 + 0] * inv;
        t.y = o[d4 * 4 + 1] * inv;
        t.z = o[d4 * 4 + 2] * inv;
        t.w = o[d4 * 4 + 3] * inv;
        *reinterpret_cast<float4*>(Og + d4 * 4) = t;
    }
}

// ---------------------------------------------------------------------------
extern "C" void kernel_launch(void* const* d_in, const int* in_sizes, int n_in,
                              void* d_out, int out_size)
{
    const float* X     = (const float*)d_in[0];   // [B,S,D]
    const float* W_qkv = (const float*)d_in[1];   // [D,3D]
    const float* b_qkv = (const float*)d_in[2];   // [3D]
    const float* W_out = (const float*)d_in[3];   // [D,D]
    const float* b_out = (const float*)d_in[4];   // [D]
    float* out = (float*)d_out;                   // [B,S,D]

    // 1) QKV projection -> scatter into g_q/g_k/g_v [b,h,s,hd]
    {
        dim3 grid((3 * Dc) / 128, Mtot / 128);    // (24, 32)
        sgemm128<0><<<grid, 256>>>(X, W_qkv, b_qkv, nullptr, Mtot, 3 * Dc, Dc);
    }

    // 2) causal flash attention -> g_attn [b,s,D]
    {
        dim3 grid(Sc / 128, Bc * Hc);             // (16, 32)
        attn_kernel<<<grid, 128>>>();
    }

    // 3) output projection -> d_out
    {
        dim3 grid(Dc / 128, Mtot / 128);          // (8, 32)
        sgemm128<1><<<grid, 256>>>(nullptr, W_out, b_out, out, Mtot, Dc, Dc);
    }
}

// round 2
// speedup vs baseline: 1.0198x; 1.0198x over previous
#include <cuda_runtime.h>
#include <math.h>

// Problem constants
#define Bc   2
#define Sc   2048
#define Dc   1024
#define Hc   16
#define HDc  64
#define Mtot (Bc * Sc)          // 4096
#define SCALE 0.03125f          // 1/sqrt(1024)

typedef unsigned long long u64;

// ---------------- f32x2 packed helpers (sm_103a) ----------------
__device__ __forceinline__ u64 splat2(float x) {
    u64 r; asm("mov.b64 %0, {%1, %1};" : "=l"(r) : "f"(x)); return r;
}
__device__ __forceinline__ u64 pack2(float lo, float hi) {
    u64 r; asm("mov.b64 %0, {%1, %2};" : "=l"(r) : "f"(lo), "f"(hi)); return r;
}
__device__ __forceinline__ void unpack2(u64 v, float& lo, float& hi) {
    asm("mov.b64 {%0, %1}, %2;" : "=f"(lo), "=f"(hi) : "l"(v));
}
__device__ __forceinline__ void fma2(u64& d, u64 a, u64 b) {
    asm("fma.rn.f32x2 %0, %1, %2, %0;" : "+l"(d) : "l"(a), "l"(b));
}
__device__ __forceinline__ u64 mul2(u64 a, u64 b) {
    u64 d; asm("mul.rn.f32x2 %0, %1, %2;" : "=l"(d) : "l"(a), "l"(b)); return d;
}

// Scratch (device globals: alloc-free rule)
__device__ float g_q[(size_t)Bc * Hc * Sc * HDc];     // [b,h,s,d] 16 MB
__device__ float g_k[(size_t)Bc * Hc * Sc * HDc];
__device__ float g_v[(size_t)Bc * Hc * Sc * HDc];
__device__ float g_attn[(size_t)Bc * Sc * Dc];        // [b,s,D]  16 MB

// ---------------------------------------------------------------------------
// Tiled SGEMM with packed f32x2 FMAs: C[M,N] = A[M,K] @ B[K,N] + bias[N]
// 128x128 block tile, BK=8, 256 threads, 8x8 micro-tile (stored as 8x4 f32x2).
// MODE 0: epilogue scatters into g_q/g_k/g_v ([b,h,s,hd]); MODE 1: plain + bias.
// ---------------------------------------------------------------------------
template <int MODE>
__global__ __launch_bounds__(256)
void sgemm128(const float* __restrict__ A, const float* __restrict__ Bm,
              const float* __restrict__ bias, float* __restrict__ C,
              int M, int N, int K)
{
    __shared__ __align__(16) float As[8][128];   // transposed A tile
    __shared__ __align__(16) float Bs[8][128];

    const int tid = threadIdx.x;
    const int bm = blockIdx.y * 128;
    const int bn = blockIdx.x * 128;

    const int aRow = tid >> 1;            // 0..127
    const int aCol = (tid & 1) << 2;      // 0 or 4
    const int bRow = tid >> 5;            // 0..7
    const int bCol = (tid & 31) << 2;     // 0..124

    const int tx = tid & 15;              // col micro-tile
    const int ty = tid >> 4;              // row micro-tile

    const float* Ap = (MODE == 1) ? g_attn : A;

    u64 acc2[8][4];
#pragma unroll
    for (int i = 0; i < 8; i++)
#pragma unroll
        for (int j = 0; j < 4; j++) acc2[i][j] = 0ull;

    const float* Aload = Ap + (size_t)(bm + aRow) * K + aCol;
    const float* Bload = Bm + (size_t)bRow * N + bn + bCol;

    for (int k0 = 0; k0 < K; k0 += 8) {
        float4 a4 = *reinterpret_cast<const float4*>(Aload + k0);
        float4 b4 = *reinterpret_cast<const float4*>(Bload + (size_t)k0 * N);
        As[aCol + 0][aRow] = a4.x;
        As[aCol + 1][aRow] = a4.y;
        As[aCol + 2][aRow] = a4.z;
        As[aCol + 3][aRow] = a4.w;
        *reinterpret_cast<float4*>(&Bs[bRow][bCol]) = b4;
        __syncthreads();

#pragma unroll
        for (int kk = 0; kk < 8; kk++) {
            float4 ra0 = *reinterpret_cast<const float4*>(&As[kk][ty * 8]);
            float4 ra1 = *reinterpret_cast<const float4*>(&As[kk][ty * 8 + 4]);
            const ulonglong2* bp = reinterpret_cast<const ulonglong2*>(&Bs[kk][tx * 8]);
            ulonglong2 b01 = bp[0];
            ulonglong2 b23 = bp[1];
            u64 rb2[4] = {b01.x, b01.y, b23.x, b23.y};
            float ra[8] = {ra0.x, ra0.y, ra0.z, ra0.w, ra1.x, ra1.y, ra1.z, ra1.w};
#pragma unroll
            for (int i = 0; i < 8; i++) {
                u64 a2 = splat2(ra[i]);
#pragma unroll
                for (int j = 0; j < 4; j++)
                    fma2(acc2[i][j], a2, rb2[j]);
            }
        }
        __syncthreads();
    }

    // unpack accumulators
    float acc[8][8];
#pragma unroll
    for (int i = 0; i < 8; i++)
#pragma unroll
        for (int j = 0; j < 4; j++)
            unpack2(acc2[i][j], acc[i][j * 2], acc[i][j * 2 + 1]);

    const int col0 = bn + tx * 8;
    float bv[8];
    {
        float4 bb0 = *reinterpret_cast<const float4*>(bias + col0);
        float4 bb1 = *reinterpret_cast<const float4*>(bias + col0 + 4);
        bv[0] = bb0.x; bv[1] = bb0.y; bv[2] = bb0.z; bv[3] = bb0.w;
        bv[4] = bb1.x; bv[5] = bb1.y; bv[6] = bb1.z; bv[7] = bb1.w;
    }

    if (MODE == 1) {
#pragma unroll
        for (int i = 0; i < 8; i++) {
            const int row = bm + ty * 8 + i;
            float4 o0, o1;
            o0.x = acc[i][0] + bv[0]; o0.y = acc[i][1] + bv[1];
            o0.z = acc[i][2] + bv[2]; o0.w = acc[i][3] + bv[3];
            o1.x = acc[i][4] + bv[4]; o1.y = acc[i][5] + bv[5];
            o1.z = acc[i][6] + bv[6]; o1.w = acc[i][7] + bv[7];
            *reinterpret_cast<float4*>(C + (size_t)row * N + col0) = o0;
            *reinterpret_cast<float4*>(C + (size_t)row * N + col0 + 4) = o1;
        }
    } else {
        const int qkv = col0 >> 10;           // 0,1,2
        const int rest = col0 & 1023;
        const int h = rest >> 6;
        const int c0 = rest & 63;
        float* dstBase = (qkv == 0) ? g_q : ((qkv == 1) ? g_k : g_v);
#pragma unroll
        for (int i = 0; i < 8; i++) {
            const int m = bm + ty * 8 + i;
            const int b = m >> 11;            // /S (2048)
            const int s = m & (Sc - 1);
            float* dst = dstBase + ((((size_t)b * Hc + h) * Sc + s) * HDc + c0);
            float4 o0, o1;
            o0.x = acc[i][0] + bv[0]; o0.y = acc[i][1] + bv[1];
            o0.z = acc[i][2] + bv[2]; o0.w = acc[i][3] + bv[3];
            o1.x = acc[i][4] + bv[4]; o1.y = acc[i][5] + bv[5];
            o1.z = acc[i][6] + bv[6]; o1.w = acc[i][7] + bv[7];
            *reinterpret_cast<float4*>(dst) = o0;
            *reinterpret_cast<float4*>(dst + 4) = o1;
        }
    }
}

// ---------------------------------------------------------------------------
// Flash attention fp32 with packed f32x2. One query per thread.
// Grid: (S/128, B*H), 128 threads. Keys processed in chunks of 4 with one
// online-softmax rescale per chunk. Causal via per-key -inf mask.
// ---------------------------------------------------------------------------
#define TKEYS 64

__global__ __launch_bounds__(128)
void attn_kernel()
{
    const int bh = blockIdx.y;                      // 0..B*H-1
    const int b = bh / Hc;
    const int h = bh % Hc;
    const int qi = blockIdx.x * 128 + threadIdx.x;  // query index

    __shared__ __align__(16) float Ks[TKEYS][HDc];
    __shared__ __align__(16) float Vs[TKEYS][HDc];

    // Load q packed (scale folded in): 32 f32x2
    u64 q2[HDc / 2];
    {
        const float* Qg = g_q + ((size_t)bh * Sc + qi) * HDc;
#pragma unroll
        for (int d4 = 0; d4 < HDc / 4; d4++) {
            float4 t = *reinterpret_cast<const float4*>(Qg + d4 * 4);
            q2[d4 * 2 + 0] = pack2(t.x * SCALE, t.y * SCALE);
            q2[d4 * 2 + 1] = pack2(t.z * SCALE, t.w * SCALE);
        }
    }

    u64 o2[HDc / 2];
#pragma unroll
    for (int d = 0; d < HDc / 2; d++) o2[d] = 0ull;
    float mrun = -INFINITY;
    float lrun = 0.f;

    const int kmax = blockIdx.x * 128 + 127;        // max key this block needs
    const float* Kg0 = g_k + (size_t)bh * Sc * HDc;
    const float* Vg0 = g_v + (size_t)bh * Sc * HDc;

    for (int kt = 0; kt <= kmax; kt += TKEYS) {
        // cooperative tile load
        {
            const float4* Kg = reinterpret_cast<const float4*>(Kg0 + (size_t)kt * HDc);
            const float4* Vg = reinterpret_cast<const float4*>(Vg0 + (size_t)kt * HDc);
            float4* Kd = reinterpret_cast<float4*>(&Ks[0][0]);
            float4* Vd = reinterpret_cast<float4*>(&Vs[0][0]);
#pragma unroll
            for (int i = 0; i < (TKEYS * HDc / 4) / 128; i++) {
                Kd[threadIdx.x + i * 128] = Kg[threadIdx.x + i * 128];
                Vd[threadIdx.x + i * 128] = Vg[threadIdx.x + i * 128];
            }
        }
        __syncthreads();

        const int klim = min(TKEYS, qi - kt + 1);   // causal bound (can be <=0)
        for (int kk = 0; kk < klim; kk += 4) {
            // ---- scores for 4 keys ----
            u64 s2[4] = {0ull, 0ull, 0ull, 0ull};
#pragma unroll
            for (int j = 0; j < 4; j++) {
                const ulonglong2* kp = reinterpret_cast<const ulonglong2*>(&Ks[kk + j][0]);
#pragma unroll
                for (int d = 0; d < HDc / 4; d++) {
                    ulonglong2 kv = kp[d];
                    fma2(s2[j], q2[d * 2 + 0], kv.x);
                    fma2(s2[j], q2[d * 2 + 1], kv.y);
                }
            }
            float s[4];
#pragma unroll
            for (int j = 0; j < 4; j++) {
                float lo, hi; unpack2(s2[j], lo, hi);
                s[j] = lo + hi;
                if (kt + kk + j > qi) s[j] = -INFINITY;   // causal / chunk-tail mask
            }
            const float m4 = fmaxf(fmaxf(s[0], s[1]), fmaxf(s[2], s[3]));
            if (m4 > mrun) {
                const float corr = __expf(mrun - m4);     // 0 when mrun == -inf
                mrun = m4;
                lrun *= corr;
                const u64 c2 = splat2(corr);
#pragma unroll
                for (int d = 0; d < HDc / 2; d++) o2[d] = mul2(o2[d], c2);
            }
            float p[4];
#pragma unroll
            for (int j = 0; j < 4; j++) p[j] = __expf(s[j] - mrun);  // masked -> 0
            lrun += (p[0] + p[1]) + (p[2] + p[3]);

            u64 p2[4];
#pragma unroll
            for (int j = 0; j < 4; j++) p2[j] = splat2(p[j]);
#pragma unroll
            for (int j = 0; j < 4; j++) {
                const ulonglong2* vp = reinterpret_cast<const ulonglong2*>(&Vs[kk + j][0]);
#pragma unroll
                for (int d = 0; d < HDc / 4; d++) {
                    ulonglong2 vv = vp[d];
                    fma2(o2[d * 2 + 0], p2[j], vv.x);
                    fma2(o2[d * 2 + 1], p2[j], vv.y);
                }
            }
        }
        __syncthreads();
    }

    const float inv = 1.f / lrun;
    float* Og = g_attn + ((size_t)b * Sc + qi) * Dc + h * HDc;
#pragma unroll
    for (int d4 = 0; d4 < HDc / 4; d4++) {
        float a0, a1, a2v, a3;
        unpack2(o2[d4 * 2 + 0], a0, a1);
        unpack2(o2[d4 * 2 + 1], a2v, a3);
        float4 t;
        t.x = a0 * inv; t.y = a1 * inv; t.z = a2v * inv; t.w = a3 * inv;
        *reinterpret_cast<float4*>(Og + d4 * 4) = t;
    }
}

// ---------------------------------------------------------------------------
extern "C" void kernel_launch(void* const* d_in, const int* in_sizes, int n_in,
                              void* d_out, int out_size)
{
    const float* X     = (const float*)d_in[0];   // [B,S,D]
    const float* W_qkv = (const float*)d_in[1];   // [D,3D]
    const float* b_qkv = (const float*)d_in[2];   // [3D]
    const float* W_out = (const float*)d_in[3];   // [D,D]
    const float* b_out = (const float*)d_in[4];   // [D]
    float* out = (float*)d_out;                   // [B,S,D]

    // 1) QKV projection -> scatter into g_q/g_k/g_v [b,h,s,hd]
    {
        dim3 grid((3 * Dc) / 128, Mtot / 128);    // (24, 32)
        sgemm128<0><<<grid, 256>>>(X, W_qkv, b_qkv, nullptr, Mtot, 3 * Dc, Dc);
    }

    // 2) causal flash attention -> g_attn [b,s,D]
    {
        dim3 grid(Sc / 128, Bc * Hc);             // (16, 32)
        attn_kernel<<<grid, 128>>>();
    }

    // 3) output projection -> d_out
    {
        dim3 grid(Dc / 128, Mtot / 128);          // (8, 32)
        sgemm128<1><<<grid, 256>>>(nullptr, W_out, b_out, out, Mtot, Dc, Dc);
    }
}

// round 5
// speedup vs baseline: 1.5866x; 1.5557x over previous
#include <cuda_runtime.h>
#include <cuda_bf16.h>
#include <math.h>
#include <stdint.h>

// Problem constants
#define Bc   2
#define Sc   2048
#define Dc   1024
#define Hc   16
#define HDc  64
#define Mtot 4096
#define SCALE 0.03125f          // 1/sqrt(1024)

typedef unsigned long long u64;
typedef uint32_t u32;

// ---------------- scratch (device globals; referenced ONLY in device code) --
__device__ float g_q[(size_t)Bc * Hc * Sc * HDc];
__device__ float g_k[(size_t)Bc * Hc * Sc * HDc];
__device__ float g_v[(size_t)Bc * Hc * Sc * HDc];
__device__ float g_attn[(size_t)Bc * Sc * Dc];

__device__ __nv_bfloat16 g_ah[(size_t)Mtot * Dc];      // A hi (X or attn)
__device__ __nv_bfloat16 g_al[(size_t)Mtot * Dc];      // A lo
__device__ __nv_bfloat16 g_wqh[(size_t)3 * Dc * Dc];   // W_qkv^T hi  [N=3072, K=1024]
__device__ __nv_bfloat16 g_wql[(size_t)3 * Dc * Dc];
__device__ __nv_bfloat16 g_woh[(size_t)Dc * Dc];       // W_out^T hi  [N=1024, K=1024]
__device__ __nv_bfloat16 g_wol[(size_t)Dc * Dc];

// ---------------- PTX helpers (non-arch-specific, sm_80 class) --------------
__device__ __forceinline__ u32 smem_u32_of(const void* p) {
    u32 a;
    asm("{ .reg .u64 t; cvta.to.shared.u64 t, %1; cvt.u32.u64 %0, t; }" : "=r"(a) : "l"(p));
    return a;
}
__device__ __forceinline__ void cp16(u32 dst, const void* src) {
    asm volatile("cp.async.cg.shared.global [%0], [%1], 16;" :: "r"(dst), "l"(src));
}
#define CP_COMMIT() asm volatile("cp.async.commit_group;" ::: "memory")
#define CP_WAIT1()  asm volatile("cp.async.wait_group 1;" ::: "memory")
#define CP_WAIT0()  asm volatile("cp.async.wait_group 0;" ::: "memory")

#define LDX4(r, addr) \
    asm volatile("ldmatrix.sync.aligned.m8n8.x4.shared.b16 {%0,%1,%2,%3}, [%4];" \
        : "=r"((r)[0]), "=r"((r)[1]), "=r"((r)[2]), "=r"((r)[3]) : "r"(addr))

#define MMA16816(d, a, b0, b1) \
    asm volatile("mma.sync.aligned.m16n8k16.row.col.f32.bf16.bf16.f32 " \
        "{%0,%1,%2,%3}, {%4,%5,%6,%7}, {%8,%9}, {%0,%1,%2,%3};" \
        : "+f"((d)[0]), "+f"((d)[1]), "+f"((d)[2]), "+f"((d)[3]) \
        : "r"((a)[0]), "r"((a)[1]), "r"((a)[2]), "r"((a)[3]), "r"(b0), "r"(b1))

// ---------------- f32x2 packed helpers (attention) ----------------
__device__ __forceinline__ u64 splat2(float x) { u64 r; asm("mov.b64 %0, {%1, %1};" : "=l"(r) : "f"(x)); return r; }
__device__ __forceinline__ u64 pack2(float lo, float hi) { u64 r; asm("mov.b64 %0, {%1, %2};" : "=l"(r) : "f"(lo), "f"(hi)); return r; }
__device__ __forceinline__ void unpack2(u64 v, float& lo, float& hi) { asm("mov.b64 {%0, %1}, %2;" : "=f"(lo), "=f"(hi) : "l"(v)); }
__device__ __forceinline__ void fma2(u64& d, u64 a, u64 b) { asm("fma.rn.f32x2 %0, %1, %2, %0;" : "+l"(d) : "l"(a), "l"(b)); }
__device__ __forceinline__ u64 mul2(u64 a, u64 b) { u64 d; asm("mul.rn.f32x2 %0, %1, %2;" : "=l"(d) : "l"(a), "l"(b)); return d; }

// ---------------------------------------------------------------------------
// Split kernels: fp32 -> (hi, lo) bf16. Scratch dsts chosen DEVICE-SIDE.
// ---------------------------------------------------------------------------
// MODE 0: src = param (X). MODE 1: src = g_attn. dst = g_ah/g_al.
template <int MODE>
__global__ void split_rm(const float* __restrict__ srcp, int n4)
{
    const float* src = (MODE == 0) ? srcp : g_attn;
    __nv_bfloat16* hi = g_ah;
    __nv_bfloat16* lo = g_al;
    for (int i = blockIdx.x * blockDim.x + threadIdx.x; i < n4; i += gridDim.x * blockDim.x) {
        float4 v = reinterpret_cast<const float4*>(src)[i];
        __nv_bfloat16 h0 = __float2bfloat16_rn(v.x), h1 = __float2bfloat16_rn(v.y);
        __nv_bfloat16 h2 = __float2bfloat16_rn(v.z), h3 = __float2bfloat16_rn(v.w);
        __nv_bfloat16 l0 = __float2bfloat16_rn(v.x - __bfloat162float(h0));
        __nv_bfloat16 l1 = __float2bfloat16_rn(v.y - __bfloat162float(h1));
        __nv_bfloat16 l2 = __float2bfloat16_rn(v.z - __bfloat162float(h2));
        __nv_bfloat16 l3 = __float2bfloat16_rn(v.w - __bfloat162float(h3));
        __nv_bfloat162 hp0(h0, h1), hp1(h2, h3), lp0(l0, l1), lp1(l2, l3);
        uint2 hv, lv;
        hv.x = *reinterpret_cast<u32*>(&hp0); hv.y = *reinterpret_cast<u32*>(&hp1);
        lv.x = *reinterpret_cast<u32*>(&lp0); lv.y = *reinterpret_cast<u32*>(&lp1);
        reinterpret_cast<uint2*>(hi)[i] = hv;
        reinterpret_cast<uint2*>(lo)[i] = lv;
    }
}

// W [Kd, Nd] row-major -> hi/lo [Nd, Kd]. MODE 0 -> g_wqh/g_wql, MODE 1 -> g_woh/g_wol.
template <int MODE>
__global__ void split_tr(const float* __restrict__ W, int Kd, int Nd)
{
    __nv_bfloat16* hi = (MODE == 0) ? g_wqh : g_woh;
    __nv_bfloat16* lo = (MODE == 0) ? g_wql : g_wol;
    __shared__ float t[32][33];
    const int n0 = blockIdx.x * 32, k0 = blockIdx.y * 32;
    const int tx = threadIdx.x, ty = threadIdx.y;
#pragma unroll
    for (int i = 0; i < 4; i++)
        t[ty + i * 8][tx] = W[(size_t)(k0 + ty + i * 8) * Nd + n0 + tx];
    __syncthreads();
#pragma unroll
    for (int i = 0; i < 4; i++) {
        const int nn = ty + i * 8;
        float v = t[tx][nn];
        __nv_bfloat16 h = __float2bfloat16_rn(v);
        __nv_bfloat16 l = __float2bfloat16_rn(v - __bfloat162float(h));
        hi[(size_t)(n0 + nn) * Kd + k0 + tx] = h;
        lo[(size_t)(n0 + nn) * Kd + k0 + tx] = l;
    }
}

// ---------------------------------------------------------------------------
// mma.sync bf16-split GEMM: C[M,N] = A[M,K] @ B^T + bias,  B stored [N,K].
// 128x128 tile, KC=64, cp.async double buffer, 8 warps (2x4), warp tile 64x32.
// MODE 0: A=g_ah/g_al, B=g_wqh/g_wql, scatter into g_q/g_k/g_v.
// MODE 1: A=g_ah/g_al, B=g_woh/g_wol, write C (+bias).
// ---------------------------------------------------------------------------
#define KC        64
#define TILE_B    16384          // 128 rows x 128 bytes (64 bf16)
#define OFF_AH    0
#define OFF_AL    TILE_B
#define OFF_BH    (2 * TILE_B)
#define OFF_BL    (3 * TILE_B)
#define STAGE_B   (4 * TILE_B)   // 64 KB
#define GEMM_SMEM (2 * STAGE_B)  // 128 KB

__device__ __forceinline__ void load_chunk(u32 stg,
    const __nv_bfloat16* __restrict__ Ah, const __nv_bfloat16* __restrict__ Al,
    const __nv_bfloat16* __restrict__ Bh, const __nv_bfloat16* __restrict__ Bl,
    int bm, int bn, int col0, int K, int tid)
{
#pragma unroll
    for (int i = 0; i < 4; i++) {
        const int idx = i * 256 + tid;
        const int r = idx >> 3, cc = idx & 7;
        u32 off = (u32)((r << 7) + (cc << 4));
        off ^= (off >> 3) & 0x70;
        const size_t aoff = (size_t)(bm + r) * K + col0 + cc * 8;
        const size_t boff = (size_t)(bn + r) * K + col0 + cc * 8;
        cp16(stg + OFF_AH + off, Ah + aoff);
        cp16(stg + OFF_AL + off, Al + aoff);
        cp16(stg + OFF_BH + off, Bh + boff);
        cp16(stg + OFF_BL + off, Bl + boff);
    }
}

template <int MODE>
__global__ __launch_bounds__(256, 1)
void gemm_mma(const float* __restrict__ bias, float* __restrict__ C, int N, int K)
{
    const __nv_bfloat16* Ah = g_ah;
    const __nv_bfloat16* Al = g_al;
    const __nv_bfloat16* Bh = (MODE == 0) ? g_wqh : g_woh;
    const __nv_bfloat16* Bl = (MODE == 0) ? g_wql : g_wol;

    extern __shared__ char smem[];
    const u32 sbase = smem_u32_of(smem);
    const int tid = threadIdx.x;
    const int bm = blockIdx.y * 128;
    const int bn = blockIdx.x * 128;
    const int lane = tid & 31, warp = tid >> 5;
    const int m0w = (warp >> 2) * 64;     // 0 or 64
    const int n0w = (warp & 3) * 32;      // 0,32,64,96

    float acc[4][4][4];
#pragma unroll
    for (int mi = 0; mi < 4; mi++)
#pragma unroll
        for (int ni = 0; ni < 4; ni++)
#pragma unroll
            for (int q = 0; q < 4; q++) acc[mi][ni][q] = 0.f;

    const int aRowOff = lane & 15;
    const u32 aKb = (u32)((lane >> 4) << 4);
    const int bRowOff = ((lane >> 4) & 1) * 8 + (lane & 7);
    const u32 bKb = (u32)(((lane >> 3) & 1) << 4);

    const int NC = K / KC;   // 16

    load_chunk(sbase, Ah, Al, Bh, Bl, bm, bn, 0, K, tid);
    CP_COMMIT();

    for (int c = 0; c < NC; c++) {
        const u32 stg = sbase + (u32)(c & 1) * STAGE_B;
        if (c + 1 < NC) {
            load_chunk(sbase + (u32)((c + 1) & 1) * STAGE_B, Ah, Al, Bh, Bl, bm, bn, (c + 1) * KC, K, tid);
            CP_COMMIT();
            CP_WAIT1();
        } else {
            CP_WAIT0();
        }
        __syncthreads();

#pragma unroll
        for (int k16 = 0; k16 < 4; k16++) {
            u32 fAh[4][4], fAl[4][4];
#pragma unroll
            for (int mi = 0; mi < 4; mi++) {
                u32 off = (u32)(m0w + mi * 16 + aRowOff) * 128 + aKb + (u32)k16 * 32;
                off ^= (off >> 3) & 0x70;
                LDX4(fAh[mi], stg + OFF_AH + off);
                LDX4(fAl[mi], stg + OFF_AL + off);
            }
            u32 fBh[2][4], fBl[2][4];
#pragma unroll
            for (int bi = 0; bi < 2; bi++) {
                u32 off = (u32)(n0w + bi * 16 + bRowOff) * 128 + bKb + (u32)k16 * 32;
                off ^= (off >> 3) & 0x70;
                LDX4(fBh[bi], stg + OFF_BH + off);
                LDX4(fBl[bi], stg + OFF_BL + off);
            }
#pragma unroll
            for (int mi = 0; mi < 4; mi++) {
#pragma unroll
                for (int ni = 0; ni < 4; ni++) {
                    const u32 bh0 = fBh[ni >> 1][(ni & 1) * 2], bh1 = fBh[ni >> 1][(ni & 1) * 2 + 1];
                    const u32 bl0 = fBl[ni >> 1][(ni & 1) * 2], bl1 = fBl[ni >> 1][(ni & 1) * 2 + 1];
                    MMA16816(acc[mi][ni], fAh[mi], bh0, bh1);
                    MMA16816(acc[mi][ni], fAh[mi], bl0, bl1);
                    MMA16816(acc[mi][ni], fAl[mi], bh0, bh1);
                }
            }
        }
        __syncthreads();
    }

    // epilogue
#pragma unroll
    for (int ni = 0; ni < 4; ni++) {
        const int g = bn + n0w + ni * 8 + (lane & 3) * 2;
        const float bv0 = bias[g], bv1 = bias[g + 1];
        if (MODE == 1) {
#pragma unroll
            for (int mi = 0; mi < 4; mi++) {
                const int r0 = bm + m0w + mi * 16 + (lane >> 2);
                float2 v0 = {acc[mi][ni][0] + bv0, acc[mi][ni][1] + bv1};
                float2 v1 = {acc[mi][ni][2] + bv0, acc[mi][ni][3] + bv1};
                *reinterpret_cast<float2*>(C + (size_t)r0 * N + g) = v0;
                *reinterpret_cast<float2*>(C + (size_t)(r0 + 8) * N + g) = v1;
            }
        } else {
            const int qkv = g >> 10;
            const int h = (g & 1023) >> 6;
            const int c0 = g & 63;
            float* base = (qkv == 0) ? g_q : ((qkv == 1) ? g_k : g_v);
#pragma unroll
            for (int mi = 0; mi < 4; mi++) {
#pragma unroll
                for (int half = 0; half < 2; half++) {
                    const int row = bm + m0w + mi * 16 + (lane >> 2) + half * 8;
                    const int b = row >> 11;
                    const int sI = row & (Sc - 1);
                    float2 v = {acc[mi][ni][half * 2 + 0] + bv0, acc[mi][ni][half * 2 + 1] + bv1};
                    *reinterpret_cast<float2*>(base + ((((size_t)b * Hc + h) * Sc + sI) * HDc + c0)) = v;
                }
            }
        }
    }
}

// ---------------------------------------------------------------------------
// Flash attention fp32 (f32x2), one query per thread. Unchanged (passing R2).
// ---------------------------------------------------------------------------
#define TKEYS 64

__global__ __launch_bounds__(128)
void attn_kernel()
{
    const int bh = blockIdx.y;
    const int b = bh / Hc;
    const int h = bh % Hc;
    const int qi = blockIdx.x * 128 + threadIdx.x;

    __shared__ __align__(16) float Ks[TKEYS][HDc];
    __shared__ __align__(16) float Vs[TKEYS][HDc];

    u64 q2[HDc / 2];
    {
        const float* Qg = g_q + ((size_t)bh * Sc + qi) * HDc;
#pragma unroll
        for (int d4 = 0; d4 < HDc / 4; d4++) {
            float4 t = *reinterpret_cast<const float4*>(Qg + d4 * 4);
            q2[d4 * 2 + 0] = pack2(t.x * SCALE, t.y * SCALE);
            q2[d4 * 2 + 1] = pack2(t.z * SCALE, t.w * SCALE);
        }
    }

    u64 o2[HDc / 2];
#pragma unroll
    for (int d = 0; d < HDc / 2; d++) o2[d] = 0ull;
    float mrun = -INFINITY;
    float lrun = 0.f;

    const int kmax = blockIdx.x * 128 + 127;
    const float* Kg0 = g_k + (size_t)bh * Sc * HDc;
    const float* Vg0 = g_v + (size_t)bh * Sc * HDc;

    for (int kt = 0; kt <= kmax; kt += TKEYS) {
        {
            const float4* Kg = reinterpret_cast<const float4*>(Kg0 + (size_t)kt * HDc);
            const float4* Vg = reinterpret_cast<const float4*>(Vg0 + (size_t)kt * HDc);
            float4* Kd = reinterpret_cast<float4*>(&Ks[0][0]);
            float4* Vd = reinterpret_cast<float4*>(&Vs[0][0]);
#pragma unroll
            for (int i = 0; i < (TKEYS * HDc / 4) / 128; i++) {
                Kd[threadIdx.x + i * 128] = Kg[threadIdx.x + i * 128];
                Vd[threadIdx.x + i * 128] = Vg[threadIdx.x + i * 128];
            }
        }
        __syncthreads();

        const int klim = min(TKEYS, qi - kt + 1);
        for (int kk = 0; kk < klim; kk += 4) {
            u64 s2[4] = {0ull, 0ull, 0ull, 0ull};
#pragma unroll
            for (int j = 0; j < 4; j++) {
                const ulonglong2* kp = reinterpret_cast<const ulonglong2*>(&Ks[kk + j][0]);
#pragma unroll
                for (int d = 0; d < HDc / 4; d++) {
                    ulonglong2 kv = kp[d];
                    fma2(s2[j], q2[d * 2 + 0], kv.x);
                    fma2(s2[j], q2[d * 2 + 1], kv.y);
                }
            }
            float s[4];
#pragma unroll
            for (int j = 0; j < 4; j++) {
                float lo, hi; unpack2(s2[j], lo, hi);
                s[j] = lo + hi;
                if (kt + kk + j > qi) s[j] = -INFINITY;
            }
            const float m4 = fmaxf(fmaxf(s[0], s[1]), fmaxf(s[2], s[3]));
            if (m4 > mrun) {
                const float corr = __expf(mrun - m4);
                mrun = m4;
                lrun *= corr;
                const u64 c2 = splat2(corr);
#pragma unroll
                for (int d = 0; d < HDc / 2; d++) o2[d] = mul2(o2[d], c2);
            }
            float p[4];
#pragma unroll
            for (int j = 0; j < 4; j++) p[j] = __expf(s[j] - mrun);
            lrun += (p[0] + p[1]) + (p[2] + p[3]);

            u64 p2[4];
#pragma unroll
            for (int j = 0; j < 4; j++) p2[j] = splat2(p[j]);
#pragma unroll
            for (int j = 0; j < 4; j++) {
                const ulonglong2* vp = reinterpret_cast<const ulonglong2*>(&Vs[kk + j][0]);
#pragma unroll
                for (int d = 0; d < HDc / 4; d++) {
                    ulonglong2 vv = vp[d];
                    fma2(o2[d * 2 + 0], p2[j], vv.x);
                    fma2(o2[d * 2 + 1], p2[j], vv.y);
                }
            }
        }
        __syncthreads();
    }

    const float inv = 1.f / lrun;
    float* Og = g_attn + ((size_t)b * Sc + qi) * Dc + h * HDc;
#pragma unroll
    for (int d4 = 0; d4 < HDc / 4; d4++) {
        float a0, a1, a2v, a3;
        unpack2(o2[d4 * 2 + 0], a0, a1);
        unpack2(o2[d4 * 2 + 1], a2v, a3);
        float4 t = {a0 * inv, a1 * inv, a2v * inv, a3 * inv};
        *reinterpret_cast<float4*>(Og + d4 * 4) = t;
    }
}

// ---------------------------------------------------------------------------
extern "C" void kernel_launch(void* const* d_in, const int* in_sizes, int n_in,
                              void* d_out, int out_size)
{
    const float* X     = (const float*)d_in[0];
    const float* W_qkv = (const float*)d_in[1];
    const float* b_qkv = (const float*)d_in[2];
    const float* W_out = (const float*)d_in[3];
    const float* b_out = (const float*)d_in[4];
    float* out = (float*)d_out;

    cudaFuncSetAttribute(gemm_mma<0>, cudaFuncAttributeMaxDynamicSharedMemorySize, GEMM_SMEM);
    cudaFuncSetAttribute(gemm_mma<1>, cudaFuncAttributeMaxDynamicSharedMemorySize, GEMM_SMEM);

    // bf16 splits (only harness pointers passed; scratch dsts are device-side)
    split_rm<0><<<1024, 256>>>(X, Mtot * Dc / 4);
    split_tr<0><<<dim3(3 * Dc / 32, Dc / 32), dim3(32, 8)>>>(W_qkv, Dc, 3 * Dc);
    split_tr<1><<<dim3(Dc / 32, Dc / 32), dim3(32, 8)>>>(W_out, Dc, Dc);

    // 1) QKV projection (tensor cores, mma.sync) -> g_q/g_k/g_v
    gemm_mma<0><<<dim3(3 * Dc / 128, Mtot / 128), 256, GEMM_SMEM>>>(b_qkv, nullptr, 3 * Dc, Dc);

    // 2) causal flash attention -> g_attn
    attn_kernel<<<dim3(Sc / 128, Bc * Hc), 128>>>();

    // 3) split attn output, out-proj -> d_out
    split_rm<1><<<1024, 256>>>(nullptr, Mtot * Dc / 4);
    gemm_mma<1><<<dim3(Dc / 128, Mtot / 128), 256, GEMM_SMEM>>>(b_out, out, Dc, Dc);
}

// round 6
// speedup vs baseline: 3.8017x; 2.3962x over previous
#include <cuda_runtime.h>
#include <cuda_bf16.h>
#include <math.h>
#include <stdint.h>

// Problem constants
#define Bc   2
#define Sc   2048
#define Dc   1024
#define Hc   16
#define HDc  64
#define Mtot 4096
#define SCALE 0.03125f          // 1/sqrt(1024)
#define NEGINF (-1e30f)

typedef unsigned long long u64;
typedef uint32_t u32;

// ---------------- scratch (device globals; referenced ONLY in device code) --
__device__ __nv_bfloat16 g_qh[(size_t)Bc * Hc * Sc * HDc];   // [bh, s, hd], pre-scaled
__device__ __nv_bfloat16 g_ql[(size_t)Bc * Hc * Sc * HDc];
__device__ __nv_bfloat16 g_kh[(size_t)Bc * Hc * Sc * HDc];
__device__ __nv_bfloat16 g_kl[(size_t)Bc * Hc * Sc * HDc];
__device__ __nv_bfloat16 g_vh[(size_t)Bc * Hc * Sc * HDc];
__device__ __nv_bfloat16 g_vl[(size_t)Bc * Hc * Sc * HDc];

__device__ __nv_bfloat16 g_ah[(size_t)Mtot * Dc];      // A hi (X, then attn out)
__device__ __nv_bfloat16 g_al[(size_t)Mtot * Dc];
__device__ __nv_bfloat16 g_wqh[(size_t)3 * Dc * Dc];   // W_qkv^T hi  [3072, 1024]
__device__ __nv_bfloat16 g_wql[(size_t)3 * Dc * Dc];
__device__ __nv_bfloat16 g_woh[(size_t)Dc * Dc];       // W_out^T hi  [1024, 1024]
__device__ __nv_bfloat16 g_wol[(size_t)Dc * Dc];

// ---------------- PTX helpers (non-arch-specific, sm_80 class) --------------
__device__ __forceinline__ u32 smem_u32_of(const void* p) {
    u32 a;
    asm("{ .reg .u64 t; cvta.to.shared.u64 t, %1; cvt.u32.u64 %0, t; }" : "=r"(a) : "l"(p));
    return a;
}
__device__ __forceinline__ void cp16(u32 dst, const void* src) {
    asm volatile("cp.async.cg.shared.global [%0], [%1], 16;" :: "r"(dst), "l"(src));
}
#define CP_COMMIT() asm volatile("cp.async.commit_group;" ::: "memory")
#define CP_WAIT1()  asm volatile("cp.async.wait_group 1;" ::: "memory")
#define CP_WAIT0()  asm volatile("cp.async.wait_group 0;" ::: "memory")

#define LDX4(r, addr) \
    asm volatile("ldmatrix.sync.aligned.m8n8.x4.shared.b16 {%0,%1,%2,%3}, [%4];" \
        : "=r"((r)[0]), "=r"((r)[1]), "=r"((r)[2]), "=r"((r)[3]) : "r"(addr))
#define LDX4T(r, addr) \
    asm volatile("ldmatrix.sync.aligned.m8n8.x4.trans.shared.b16 {%0,%1,%2,%3}, [%4];" \
        : "=r"((r)[0]), "=r"((r)[1]), "=r"((r)[2]), "=r"((r)[3]) : "r"(addr))

#define MMA16816(d, a, b0, b1) \
    asm volatile("mma.sync.aligned.m16n8k16.row.col.f32.bf16.bf16.f32 " \
        "{%0,%1,%2,%3}, {%4,%5,%6,%7}, {%8,%9}, {%0,%1,%2,%3};" \
        : "+f"((d)[0]), "+f"((d)[1]), "+f"((d)[2]), "+f"((d)[3]) \
        : "r"((a)[0]), "r"((a)[1]), "r"((a)[2]), "r"((a)[3]), "r"(b0), "r"(b1))

// split v0,v1 (fp32) -> packed bf16x2 hi + lo residual
__device__ __forceinline__ void split_pack(float v0, float v1, u32& h, u32& l) {
    __nv_bfloat162 hb = __floats2bfloat162_rn(v0, v1);
    h = *reinterpret_cast<u32*>(&hb);
    float r0 = v0 - __low2float(hb);
    float r1 = v1 - __high2float(hb);
    __nv_bfloat162 lb = __floats2bfloat162_rn(r0, r1);
    l = *reinterpret_cast<u32*>(&lb);
}

// ---------------------------------------------------------------------------
// Split kernels: fp32 -> (hi, lo) bf16
// ---------------------------------------------------------------------------
__global__ void split_rm(const float* __restrict__ src, int n4)
{
    __nv_bfloat16* hi = g_ah;
    __nv_bfloat16* lo = g_al;
    for (int i = blockIdx.x * blockDim.x + threadIdx.x; i < n4; i += gridDim.x * blockDim.x) {
        float4 v = reinterpret_cast<const float4*>(src)[i];
        uint2 hv, lv;
        split_pack(v.x, v.y, hv.x, lv.x);
        split_pack(v.z, v.w, hv.y, lv.y);
        reinterpret_cast<uint2*>(hi)[i] = hv;
        reinterpret_cast<uint2*>(lo)[i] = lv;
    }
}

// W [Kd, Nd] row-major -> hi/lo [Nd, Kd]. MODE 0 -> g_wqh/g_wql, MODE 1 -> g_woh/g_wol.
template <int MODE>
__global__ void split_tr(const float* __restrict__ W, int Kd, int Nd)
{
    __nv_bfloat16* hi = (MODE == 0) ? g_wqh : g_woh;
    __nv_bfloat16* lo = (MODE == 0) ? g_wql : g_wol;
    __shared__ float t[32][33];
    const int n0 = blockIdx.x * 32, k0 = blockIdx.y * 32;
    const int tx = threadIdx.x, ty = threadIdx.y;
#pragma unroll
    for (int i = 0; i < 4; i++)
        t[ty + i * 8][tx] = W[(size_t)(k0 + ty + i * 8) * Nd + n0 + tx];
    __syncthreads();
#pragma unroll
    for (int i = 0; i < 4; i++) {
        const int nn = ty + i * 8;
        float v = t[tx][nn];
        __nv_bfloat16 h = __float2bfloat16_rn(v);
        __nv_bfloat16 l = __float2bfloat16_rn(v - __bfloat162float(h));
        hi[(size_t)(n0 + nn) * Kd + k0 + tx] = h;
        lo[(size_t)(n0 + nn) * Kd + k0 + tx] = l;
    }
}

// ---------------------------------------------------------------------------
// mma.sync bf16-split GEMM (as R5). MODE 0: epilogue -> bf16 hi/lo Q(scaled)/K/V.
// MODE 1: plain fp32 epilogue + bias -> C.
// ---------------------------------------------------------------------------
#define KC        64
#define TILE_B    16384
#define OFF_AH    0
#define OFF_AL    TILE_B
#define OFF_BH    (2 * TILE_B)
#define OFF_BL    (3 * TILE_B)
#define STAGE_B   (4 * TILE_B)
#define GEMM_SMEM (2 * STAGE_B)

__device__ __forceinline__ void load_chunk(u32 stg,
    const __nv_bfloat16* __restrict__ Ah, const __nv_bfloat16* __restrict__ Al,
    const __nv_bfloat16* __restrict__ Bh, const __nv_bfloat16* __restrict__ Bl,
    int bm, int bn, int col0, int K, int tid)
{
#pragma unroll
    for (int i = 0; i < 4; i++) {
        const int idx = i * 256 + tid;
        const int r = idx >> 3, cc = idx & 7;
        u32 off = (u32)((r << 7) + (cc << 4));
        off ^= (off >> 3) & 0x70;
        const size_t aoff = (size_t)(bm + r) * K + col0 + cc * 8;
        const size_t boff = (size_t)(bn + r) * K + col0 + cc * 8;
        cp16(stg + OFF_AH + off, Ah + aoff);
        cp16(stg + OFF_AL + off, Al + aoff);
        cp16(stg + OFF_BH + off, Bh + boff);
        cp16(stg + OFF_BL + off, Bl + boff);
    }
}

template <int MODE>
__global__ __launch_bounds__(256, 1)
void gemm_mma(const float* __restrict__ bias, float* __restrict__ C, int N, int K)
{
    const __nv_bfloat16* Ah = g_ah;
    const __nv_bfloat16* Al = g_al;
    const __nv_bfloat16* Bh = (MODE == 0) ? g_wqh : g_woh;
    const __nv_bfloat16* Bl = (MODE == 0) ? g_wql : g_wol;

    extern __shared__ char smem[];
    const u32 sbase = smem_u32_of(smem);
    const int tid = threadIdx.x;
    const int bm = blockIdx.y * 128;
    const int bn = blockIdx.x * 128;
    const int lane = tid & 31, warp = tid >> 5;
    const int m0w = (warp >> 2) * 64;
    const int n0w = (warp & 3) * 32;

    float acc[4][4][4];
#pragma unroll
    for (int mi = 0; mi < 4; mi++)
#pragma unroll
        for (int ni = 0; ni < 4; ni++)
#pragma unroll
            for (int q = 0; q < 4; q++) acc[mi][ni][q] = 0.f;

    const int aRowOff = lane & 15;
    const u32 aKb = (u32)((lane >> 4) << 4);
    const int bRowOff = ((lane >> 4) & 1) * 8 + (lane & 7);
    const u32 bKb = (u32)(((lane >> 3) & 1) << 4);

    const int NC = K / KC;

    load_chunk(sbase, Ah, Al, Bh, Bl, bm, bn, 0, K, tid);
    CP_COMMIT();

    for (int c = 0; c < NC; c++) {
        const u32 stg = sbase + (u32)(c & 1) * STAGE_B;
        if (c + 1 < NC) {
            load_chunk(sbase + (u32)((c + 1) & 1) * STAGE_B, Ah, Al, Bh, Bl, bm, bn, (c + 1) * KC, K, tid);
            CP_COMMIT();
            CP_WAIT1();
        } else {
            CP_WAIT0();
        }
        __syncthreads();

#pragma unroll
        for (int k16 = 0; k16 < 4; k16++) {
            u32 fAh[4][4], fAl[4][4];
#pragma unroll
            for (int mi = 0; mi < 4; mi++) {
                u32 off = (u32)(m0w + mi * 16 + aRowOff) * 128 + aKb + (u32)k16 * 32;
                off ^= (off >> 3) & 0x70;
                LDX4(fAh[mi], stg + OFF_AH + off);
                LDX4(fAl[mi], stg + OFF_AL + off);
            }
            u32 fBh[2][4], fBl[2][4];
#pragma unroll
            for (int bi = 0; bi < 2; bi++) {
                u32 off = (u32)(n0w + bi * 16 + bRowOff) * 128 + bKb + (u32)k16 * 32;
                off ^= (off >> 3) & 0x70;
                LDX4(fBh[bi], stg + OFF_BH + off);
                LDX4(fBl[bi], stg + OFF_BL + off);
            }
#pragma unroll
            for (int mi = 0; mi < 4; mi++) {
#pragma unroll
                for (int ni = 0; ni < 4; ni++) {
                    const u32 bh0 = fBh[ni >> 1][(ni & 1) * 2], bh1 = fBh[ni >> 1][(ni & 1) * 2 + 1];
                    const u32 bl0 = fBl[ni >> 1][(ni & 1) * 2], bl1 = fBl[ni >> 1][(ni & 1) * 2 + 1];
                    MMA16816(acc[mi][ni], fAh[mi], bh0, bh1);
                    MMA16816(acc[mi][ni], fAh[mi], bl0, bl1);
                    MMA16816(acc[mi][ni], fAl[mi], bh0, bh1);
                }
            }
        }
        __syncthreads();
    }

#pragma unroll
    for (int ni = 0; ni < 4; ni++) {
        const int g = bn + n0w + ni * 8 + (lane & 3) * 2;
        const float bv0 = bias[g], bv1 = bias[g + 1];
        if (MODE == 1) {
#pragma unroll
            for (int mi = 0; mi < 4; mi++) {
                const int r0 = bm + m0w + mi * 16 + (lane >> 2);
                float2 v0 = {acc[mi][ni][0] + bv0, acc[mi][ni][1] + bv1};
                float2 v1 = {acc[mi][ni][2] + bv0, acc[mi][ni][3] + bv1};
                *reinterpret_cast<float2*>(C + (size_t)r0 * N + g) = v0;
                *reinterpret_cast<float2*>(C + (size_t)(r0 + 8) * N + g) = v1;
            }
        } else {
            const int qkv = g >> 10;
            const int h = (g & 1023) >> 6;
            const int c0 = g & 63;
            const float scl = (qkv == 0) ? SCALE : 1.f;
            __nv_bfloat16* hb = (qkv == 0) ? g_qh : ((qkv == 1) ? g_kh : g_vh);
            __nv_bfloat16* lb = (qkv == 0) ? g_ql : ((qkv == 1) ? g_kl : g_vl);
#pragma unroll
            for (int mi = 0; mi < 4; mi++) {
#pragma unroll
                for (int half = 0; half < 2; half++) {
                    const int row = bm + m0w + mi * 16 + (lane >> 2) + half * 8;
                    const int b = row >> 11;
                    const int sI = row & (Sc - 1);
                    const float v0 = (acc[mi][ni][half * 2 + 0] + bv0) * scl;
                    const float v1 = (acc[mi][ni][half * 2 + 1] + bv1) * scl;
                    u32 hv, lv;
                    split_pack(v0, v1, hv, lv);
                    const size_t o = (((size_t)(b * Hc + h)) * Sc + sI) * HDc + c0;
                    *reinterpret_cast<u32*>(hb + o) = hv;
                    *reinterpret_cast<u32*>(lb + o) = lv;
                }
            }
        }
    }
}

// ---------------------------------------------------------------------------
// FlashAttention-2 with mma.sync. CTA = 128 queries, 8 warps (16 rows each).
// Key tiles of 64, cp.async double buffer. Epilogue writes bf16 hi/lo to g_ah/g_al.
// ---------------------------------------------------------------------------
#define A_QH   0
#define A_QL   16384
#define A_STG  32768            // 2 stages x 32768: {KH, KL, VH, VL} x 8192
#define ATT_SMEM (32768 + 2 * 32768)   // 96 KB

__device__ __forceinline__ void attn_load_stage(u32 stg,
    const __nv_bfloat16* Kh, const __nv_bfloat16* Kl,
    const __nv_bfloat16* Vh, const __nv_bfloat16* Vl, int kt, int tid)
{
#pragma unroll
    for (int i = 0; i < 8; i++) {
        const int idx = i * 256 + tid;
        const int tile = idx >> 9;          // constant per i
        const int r = (idx >> 3) & 63;
        const int cc = idx & 7;
        u32 off = (u32)(r * 128 + cc * 16);
        off ^= (off >> 3) & 0x70;
        const __nv_bfloat16* s = (tile == 0) ? Kh : ((tile == 1) ? Kl : ((tile == 2) ? Vh : Vl));
        cp16(stg + (u32)tile * 8192 + off, s + (size_t)(kt * 64 + r) * HDc + cc * 8);
    }
}

__global__ __launch_bounds__(256, 1)
void attn_mma()
{
    const int bh = blockIdx.y;
    const int qb = (int)gridDim.x - 1 - (int)blockIdx.x;   // big tiles first
    const int b = bh >> 4, h = bh & 15;

    extern __shared__ char smem[];
    const u32 sb = smem_u32_of(smem);
    const int tid = threadIdx.x, lane = tid & 31, warp = tid >> 5;
    const int m0w = warp * 16;

    const size_t bhoff = (size_t)bh * Sc * HDc;
    const __nv_bfloat16* Qh = g_qh + bhoff;
    const __nv_bfloat16* Ql = g_ql + bhoff;
    const __nv_bfloat16* Kh = g_kh + bhoff;
    const __nv_bfloat16* Kl = g_kl + bhoff;
    const __nv_bfloat16* Vh = g_vh + bhoff;
    const __nv_bfloat16* Vl = g_vl + bhoff;

    const int NT = 2 * qb + 2;

    // preload Q tile (hi+lo) + stage 0  (group 0)
#pragma unroll
    for (int i = 0; i < 8; i++) {
        const int idx = i * 256 + tid;
        const int hl = idx >> 10;           // constant per i
        const int r = (idx >> 3) & 127;
        const int cc = idx & 7;
        u32 off = (u32)(r * 128 + cc * 16);
        off ^= (off >> 3) & 0x70;
        const __nv_bfloat16* s = hl ? Ql : Qh;
        cp16(sb + (hl ? A_QL : A_QH) + off, s + (size_t)(qb * 128 + r) * HDc + cc * 8);
    }
    attn_load_stage(sb + A_STG, Kh, Kl, Vh, Vl, 0, tid);
    CP_COMMIT();

    // per-lane ldmatrix pieces
    const int aRowOff = lane & 15;
    const u32 aKb = (u32)((lane >> 4) << 4);
    const int bRowOff = ((lane >> 4) & 1) * 8 + (lane & 7);
    const u32 bKb = (u32)(((lane >> 3) & 1) << 4);

    u32 qfh[4][4], qfl[4][4];
    float oacc[8][4];
#pragma unroll
    for (int ni = 0; ni < 8; ni++)
#pragma unroll
        for (int q = 0; q < 4; q++) oacc[ni][q] = 0.f;
    float m0 = NEGINF, m1 = NEGINF, l0 = 0.f, l1 = 0.f;

    const int qi0 = qb * 128 + m0w + (lane >> 2);

    for (int c = 0; c < NT; c++) {
        const u32 stg = sb + A_STG + (u32)(c & 1) * 32768;
        if (c + 1 < NT) {
            attn_load_stage(sb + A_STG + (u32)((c + 1) & 1) * 32768, Kh, Kl, Vh, Vl, c + 1, tid);
            CP_COMMIT();
            CP_WAIT1();
        } else {
            CP_WAIT0();
        }
        __syncthreads();

        if (c == 0) {
#pragma unroll
            for (int kk = 0; kk < 4; kk++) {
                u32 off = (u32)(m0w + aRowOff) * 128 + aKb + (u32)kk * 32;
                off ^= (off >> 3) & 0x70;
                LDX4(qfh[kk], sb + A_QH + off);
                LDX4(qfl[kk], sb + A_QL + off);
            }
        }

        // ---- S = Q K^T ----
        float sacc[8][4];
#pragma unroll
        for (int ni = 0; ni < 8; ni++)
#pragma unroll
            for (int q = 0; q < 4; q++) sacc[ni][q] = 0.f;

#pragma unroll
        for (int kk = 0; kk < 4; kk++) {
            u32 fkh[4][4], fkl[4][4];
#pragma unroll
            for (int g = 0; g < 4; g++) {
                u32 off = (u32)(g * 16 + bRowOff) * 128 + bKb + (u32)kk * 32;
                off ^= (off >> 3) & 0x70;
                LDX4(fkh[g], stg + 0 + off);        // KH
                LDX4(fkl[g], stg + 8192 + off);     // KL
            }
#pragma unroll
            for (int ni = 0; ni < 8; ni++) {
                const u32 bh0 = fkh[ni >> 1][(ni & 1) * 2], bh1 = fkh[ni >> 1][(ni & 1) * 2 + 1];
                const u32 bl0 = fkl[ni >> 1][(ni & 1) * 2], bl1 = fkl[ni >> 1][(ni & 1) * 2 + 1];
                MMA16816(sacc[ni], qfh[kk], bh0, bh1);
                MMA16816(sacc[ni], qfl[kk], bh0, bh1);
                MMA16816(sacc[ni], qfh[kk], bl0, bl1);
            }
        }

        // ---- causal mask (only last two tiles) ----
        if (c >= 2 * qb) {
#pragma unroll
            for (int ni = 0; ni < 8; ni++) {
                const int col = c * 64 + ni * 8 + (lane & 3) * 2;
                if (col > qi0)     sacc[ni][0] = NEGINF;
                if (col + 1 > qi0) sacc[ni][1] = NEGINF;
                if (col > qi0 + 8)     sacc[ni][2] = NEGINF;
                if (col + 1 > qi0 + 8) sacc[ni][3] = NEGINF;
            }
        }

        // ---- online softmax (rows qi0, qi0+8 per thread; 4-lane quad owns a row) ----
        float mx0 = NEGINF, mx1 = NEGINF;
#pragma unroll
        for (int ni = 0; ni < 8; ni++) {
            mx0 = fmaxf(mx0, fmaxf(sacc[ni][0], sacc[ni][1]));
            mx1 = fmaxf(mx1, fmaxf(sacc[ni][2], sacc[ni][3]));
        }
        mx0 = fmaxf(mx0, __shfl_xor_sync(0xffffffffu, mx0, 1));
        mx0 = fmaxf(mx0, __shfl_xor_sync(0xffffffffu, mx0, 2));
        mx1 = fmaxf(mx1, __shfl_xor_sync(0xffffffffu, mx1, 1));
        mx1 = fmaxf(mx1, __shfl_xor_sync(0xffffffffu, mx1, 2));

        const float nm0 = fmaxf(m0, mx0), nm1 = fmaxf(m1, mx1);
        const float cr0 = __expf(m0 - nm0), cr1 = __expf(m1 - nm1);
        m0 = nm0; m1 = nm1;

        float s0 = 0.f, s1 = 0.f;
#pragma unroll
        for (int ni = 0; ni < 8; ni++) {
            sacc[ni][0] = __expf(sacc[ni][0] - nm0);
            sacc[ni][1] = __expf(sacc[ni][1] - nm0);
            sacc[ni][2] = __expf(sacc[ni][2] - nm1);
            sacc[ni][3] = __expf(sacc[ni][3] - nm1);
            s0 += sacc[ni][0] + sacc[ni][1];
            s1 += sacc[ni][2] + sacc[ni][3];
        }
        s0 += __shfl_xor_sync(0xffffffffu, s0, 1);
        s0 += __shfl_xor_sync(0xffffffffu, s0, 2);
        s1 += __shfl_xor_sync(0xffffffffu, s1, 1);
        s1 += __shfl_xor_sync(0xffffffffu, s1, 2);
        l0 = l0 * cr0 + s0;
        l1 = l1 * cr1 + s1;

#pragma unroll
        for (int ni = 0; ni < 8; ni++) {
            oacc[ni][0] *= cr0; oacc[ni][1] *= cr0;
            oacc[ni][2] *= cr1; oacc[ni][3] *= cr1;
        }

        // ---- O += P V ----
#pragma unroll
        for (int kk = 0; kk < 4; kk++) {
            u32 ph[4], pl[4];
            split_pack(sacc[2 * kk][0],     sacc[2 * kk][1],     ph[0], pl[0]);
            split_pack(sacc[2 * kk][2],     sacc[2 * kk][3],     ph[1], pl[1]);
            split_pack(sacc[2 * kk + 1][0], sacc[2 * kk + 1][1], ph[2], pl[2]);
            split_pack(sacc[2 * kk + 1][2], sacc[2 * kk + 1][3], ph[3], pl[3]);
#pragma unroll
            for (int nj = 0; nj < 4; nj++) {
                u32 fvh[4], fvl[4];
                u32 off = (u32)(kk * 16 + (lane & 15)) * 128 + (u32)nj * 32 + (u32)((lane >> 4) << 4);
                off ^= (off >> 3) & 0x70;
                LDX4T(fvh, stg + 16384 + off);      // VH
                LDX4T(fvl, stg + 24576 + off);      // VL
                MMA16816(oacc[nj * 2 + 0], ph, fvh[0], fvh[1]);
                MMA16816(oacc[nj * 2 + 0], pl, fvh[0], fvh[1]);
                MMA16816(oacc[nj * 2 + 0], ph, fvl[0], fvl[1]);
                MMA16816(oacc[nj * 2 + 1], ph, fvh[2], fvh[3]);
                MMA16816(oacc[nj * 2 + 1], pl, fvh[2], fvh[3]);
                MMA16816(oacc[nj * 2 + 1], ph, fvl[2], fvl[3]);
            }
        }
        __syncthreads();
    }

    // ---- epilogue: normalize, split hi/lo, write to g_ah/g_al ----
    const float inv0 = 1.f / l0, inv1 = 1.f / l1;
    const size_t r0off = ((size_t)b * Sc + qi0) * Dc + h * HDc;
    const size_t r1off = ((size_t)b * Sc + qi0 + 8) * Dc + h * HDc;
#pragma unroll
    for (int ni = 0; ni < 8; ni++) {
        const int col = ni * 8 + (lane & 3) * 2;
        u32 hv, lv;
        split_pack(oacc[ni][0] * inv0, oacc[ni][1] * inv0, hv, lv);
        *reinterpret_cast<u32*>(g_ah + r0off + col) = hv;
        *reinterpret_cast<u32*>(g_al + r0off + col) = lv;
        split_pack(oacc[ni][2] * inv1, oacc[ni][3] * inv1, hv, lv);
        *reinterpret_cast<u32*>(g_ah + r1off + col) = hv;
        *reinterpret_cast<u32*>(g_al + r1off + col) = lv;
    }
}

// ---------------------------------------------------------------------------
extern "C" void kernel_launch(void* const* d_in, const int* in_sizes, int n_in,
                              void* d_out, int out_size)
{
    const float* X     = (const float*)d_in[0];
    const float* W_qkv = (const float*)d_in[1];
    const float* b_qkv = (const float*)d_in[2];
    const float* W_out = (const float*)d_in[3];
    const float* b_out = (const float*)d_in[4];
    float* out = (float*)d_out;

    cudaFuncSetAttribute(gemm_mma<0>, cudaFuncAttributeMaxDynamicSharedMemorySize, GEMM_SMEM);
    cudaFuncSetAttribute(gemm_mma<1>, cudaFuncAttributeMaxDynamicSharedMemorySize, GEMM_SMEM);
    cudaFuncSetAttribute(attn_mma, cudaFuncAttributeMaxDynamicSharedMemorySize, ATT_SMEM);

    // bf16 splits
    split_rm<<<1024, 256>>>(X, Mtot * Dc / 4);
    split_tr<0><<<dim3(3 * Dc / 32, Dc / 32), dim3(32, 8)>>>(W_qkv, Dc, 3 * Dc);
    split_tr<1><<<dim3(Dc / 32, Dc / 32), dim3(32, 8)>>>(W_out, Dc, Dc);

    // 1) QKV projection -> bf16 hi/lo Q(scaled)/K/V in [bh,s,hd]
    gemm_mma<0><<<dim3(3 * Dc / 128, Mtot / 128), 256, GEMM_SMEM>>>(b_qkv, nullptr, 3 * Dc, Dc);

    // 2) causal flash attention (tensor cores) -> g_ah/g_al (hi/lo, [b,s,D])
    attn_mma<<<dim3(Sc / 128, Bc * Hc), 256, ATT_SMEM>>>();

    // 3) out-proj -> d_out
    gemm_mma<1><<<dim3(Dc / 128, Mtot / 128), 256, GEMM_SMEM>>>(b_out, out, Dc, Dc);
}